// round 13
// baseline (speedup 1.0000x reference)
#include <cuda_runtime.h>
#include <cuda_fp16.h>
#include <cstdint>
#include <math_constants.h>

#define HD 1024
#define MMR 4096
#define NR 8192
#define TK 64
#define THRESHF 0.5f

// ---------------- scratch globals ---------------------------------------------
__device__ __half g_nhi[(size_t)NR * HD];
__device__ __half g_nlo[(size_t)NR * HD];
__device__ __half g_mhi[(size_t)MMR * HD];
__device__ __half g_mlo[(size_t)MMR * HD];
__device__ __half g_wqThi[(size_t)HD * HD];
__device__ __half g_wqTlo[(size_t)HD * HD];
__device__ __half g_wohi[(size_t)HD * HD];
__device__ __half g_wolo[(size_t)HD * HD];
__device__ __half g_w2[(size_t)MMR * HD];    // mem @ Wq          [MMR, HD]
__device__ __half g_w3T[(size_t)HD * MMR];   // Wo @ mem^T        [HD, MMR]
__device__ __half g_attn[(size_t)NR * MMR];
__device__ float  g_sim[(size_t)NR * MMR];
__device__ float  g_cvec[MMR];
__device__ float  g_surprise[NR];
__device__ int    g_top_idx[TK];
__device__ float  g_top_val[TK];
__device__ int    g_slots[TK];
__device__ float  g_slot_val[TK];

// ---------------- helpers -------------------------------------------------------
__device__ __forceinline__ uint32_t smem_u32(const void* p) {
    uint32_t a;
    asm("{ .reg .u64 t; cvta.to.shared.u64 t, %1; cvt.u32.u64 %0, t; }" : "=r"(a) : "l"(p));
    return a;
}
__device__ __forceinline__ void cp16(uint32_t so, const void* gp) {
    asm volatile("cp.async.cg.shared.global [%0], [%1], 16;" :: "r"(so), "l"(gp) : "memory");
}
#define CP_COMMIT() asm volatile("cp.async.commit_group;" ::: "memory")

__device__ __forceinline__ void mma16(float* d, const uint32_t* a, uint32_t b0, uint32_t b1) {
    asm volatile(
        "mma.sync.aligned.m16n8k16.row.col.f32.f16.f16.f32 "
        "{%0,%1,%2,%3}, {%4,%5,%6,%7}, {%8,%9}, {%0,%1,%2,%3};"
        : "+f"(d[0]), "+f"(d[1]), "+f"(d[2]), "+f"(d[3])
        : "r"(a[0]), "r"(a[1]), "r"(a[2]), "r"(a[3]), "r"(b0), "r"(b1));
}
__device__ __forceinline__ void ldm4(uint32_t* r, uint32_t a) {
    asm volatile("ldmatrix.sync.aligned.m8n8.x4.shared.b16 {%0,%1,%2,%3}, [%4];"
                 : "=r"(r[0]), "=r"(r[1]), "=r"(r[2]), "=r"(r[3]) : "r"(a));
}
__device__ __forceinline__ float fexp(float x) {   // e^x on the FMA pipe
    float t = fmaxf(x * 1.44269504088896340736f, -126.f);
    float n = rintf(t);
    float f = t - n;
    float p = 1.8775767e-3f;
    p = fmaf(p, f, 8.9893397e-3f);
    p = fmaf(p, f, 5.5826318e-2f);
    p = fmaf(p, f, 2.4015361e-1f);
    p = fmaf(p, f, 6.9315308e-1f);
    p = fmaf(p, f, 1.0f);
    return p * __int_as_float(((int)n + 127) << 23);
}
__device__ __forceinline__ void split16(float v, __half& hi, __half& lo) {
    hi = __float2half_rn(v);
    lo = __float2half_rn(v - __half2float(hi));
}

// ---------------- prep + ln fused (one launch) --------------------------------------
__global__ void prepln_kernel(const float* __restrict__ memin,
                              const float* __restrict__ Wq,
                              const float* __restrict__ Wo,
                              const float* __restrict__ x,
                              const float* __restrict__ gam,
                              const float* __restrict__ bet) {
    __shared__ float tile[32][33];
    const int b = blockIdx.x, t = threadIdx.x;
    if (b < 4096) {                       // mem split
        const int i = b * 256 + t;
        const float4 v = reinterpret_cast<const float4*>(memin)[i];
        __half h[4], l[4];
        split16(v.x, h[0], l[0]); split16(v.y, h[1], l[1]);
        split16(v.z, h[2], l[2]); split16(v.w, h[3], l[3]);
        reinterpret_cast<uint2*>(g_mhi)[i] = *reinterpret_cast<uint2*>(h);
        reinterpret_cast<uint2*>(g_mlo)[i] = *reinterpret_cast<uint2*>(l);
        return;
    }
    if (b < 5120) {                       // WqT split (transpose)
        const int tb = b - 4096;
        const int r0 = (tb >> 5) * 32, c0 = (tb & 31) * 32;
        const int tx = t & 31, ty = t >> 5;
#pragma unroll
        for (int k = 0; k < 4; k++)
            tile[ty + k * 8][tx] = Wq[(size_t)(r0 + ty + k * 8) * HD + c0 + tx];
        __syncthreads();
#pragma unroll
        for (int k = 0; k < 4; k++) {
            const size_t o = (size_t)(c0 + ty + k * 8) * HD + r0 + tx;
            split16(tile[tx][ty + k * 8], g_wqThi[o], g_wqTlo[o]);
        }
        return;
    }
    if (b < 6144) {                       // Wo split
        const int i = (b - 5120) * 256 + t;
        const float4 v = reinterpret_cast<const float4*>(Wo)[i];
        __half h[4], l[4];
        split16(v.x, h[0], l[0]); split16(v.y, h[1], l[1]);
        split16(v.z, h[2], l[2]); split16(v.w, h[3], l[3]);
        reinterpret_cast<uint2*>(g_wohi)[i] = *reinterpret_cast<uint2*>(h);
        reinterpret_cast<uint2*>(g_wolo)[i] = *reinterpret_cast<uint2*>(l);
        return;
    }
    // ---- LayerNorm + surprise + fp16 split ----
    __shared__ float sh[256];
    const int row = b - 6144;
    const float* xr = x + (size_t)row * HD;
    float v[4]; float s = 0.f;
#pragma unroll
    for (int i = 0; i < 4; i++) { v[i] = xr[t + i * 256]; s += v[i]; }
    sh[t] = s; __syncthreads();
    for (int o = 128; o > 0; o >>= 1) { if (t < o) sh[t] += sh[t + o]; __syncthreads(); }
    const float mu = sh[0] * (1.f / HD);
    __syncthreads();
    float ss = 0.f;
#pragma unroll
    for (int i = 0; i < 4; i++) { float d = v[i] - mu; ss += d * d; }
    sh[t] = ss; __syncthreads();
    for (int o = 128; o > 0; o >>= 1) { if (t < o) sh[t] += sh[t + o]; __syncthreads(); }
    const float var = sh[0] * (1.f / HD);
    __syncthreads();
    const float inv = rsqrtf(var + 1e-12f);
    float as = 0.f;
#pragma unroll
    for (int i = 0; i < 4; i++) {
        const int c = t + i * 256;
        const float y = (v[i] - mu) * inv * gam[c] + bet[c];
        split16(y, g_nhi[(size_t)row * HD + c], g_nlo[(size_t)row * HD + c]);
        as += fabsf(y);
    }
    sh[t] = as; __syncthreads();
    for (int o = 128; o > 0; o >>= 1) { if (t < o) sh[t] += sh[t + o]; __syncthreads(); }
    if (t == 0) g_surprise[row] = sh[0] * (1.f / HD);
}

// ---------------- top-K via shuffle trees + scatter -----------------------------------
__device__ __forceinline__ void argmax_shfl(float& v, int& i) {
#pragma unroll
    for (int o = 16; o > 0; o >>= 1) {
        const float ov = __shfl_down_sync(0xffffffffu, v, o);
        const int   oi = __shfl_down_sync(0xffffffffu, i, o);
        if (ov > v || (ov == v && oi < i)) { v = ov; i = oi; }
    }
}

template <int PER, bool NEG>
__device__ void topk_impl(const float* __restrict__ src,
                          int* __restrict__ oidx, float* __restrict__ oval,
                          float* svv, int* svi, float* swv, int* swi) {
    const int t = threadIdx.x, lane = t & 31, w = t >> 5;
    float loc[PER];
#pragma unroll
    for (int i = 0; i < PER; i++) { float x = src[t * PER + i]; loc[i] = NEG ? -x : x; }
    for (int k = 0; k < TK; k++) {
        float bv = -CUDART_INF_F; int bi = 0x7fffffff;
#pragma unroll
        for (int i = 0; i < PER; i++)
            if (loc[i] > bv) { bv = loc[i]; bi = t * PER + i; }
        argmax_shfl(bv, bi);
        if (lane == 0) { svv[w] = bv; svi[w] = bi; }
        __syncthreads();
        if (w == 0) {
            float v2 = svv[lane]; int i2 = svi[lane];
            argmax_shfl(v2, i2);
            if (lane == 0) {
                *swv = v2; *swi = i2;
                oidx[k] = i2; oval[k] = NEG ? -v2 : v2;
            }
        }
        __syncthreads();
        const int win = *swi;
        const int rel = win - t * PER;
        if ((unsigned)rel < (unsigned)PER) loc[rel] = -CUDART_INF_F;
    }
}
__global__ void topk_scatter_kernel(const float* __restrict__ imp) {
    __shared__ float svv[32]; __shared__ int svi[32];
    __shared__ float swv;     __shared__ int swi;
    const int t = threadIdx.x;
    topk_impl<NR / 1024, false>(g_surprise, g_top_idx, g_top_val, svv, svi, &swv, &swi);
    __syncthreads();
    topk_impl<MMR / 1024, true>(imp, g_slots, g_slot_val, svv, svi, &swv, &swi);
    __syncthreads();
    for (int idx = t; idx < TK * 256; idx += 1024) {
        const int j = idx >> 8, e = idx & 255;
        if (g_top_val[j] > THRESHF) {
            const int src = g_top_idx[j], dst = g_slots[j];
            reinterpret_cast<uint2*>(g_mhi + (size_t)dst * HD)[e] =
                reinterpret_cast<const uint2*>(g_nhi + (size_t)src * HD)[e];
            reinterpret_cast<uint2*>(g_mlo + (size_t)dst * HD)[e] =
                reinterpret_cast<const uint2*>(g_nlo + (size_t)src * HD)[e];
        }
    }
}

// ---------------- softmax: g_sim (fp32, float4) -> g_attn (fp16) ----------------------
__global__ void softmax_kernel() {
    __shared__ float sh[256];
    const int row = blockIdx.x, t = threadIdx.x;
    const float4* p4 = reinterpret_cast<const float4*>(g_sim + (size_t)row * MMR);
    float4 v[4];
    float mx = -CUDART_INF_F;
#pragma unroll
    for (int i = 0; i < 4; i++) {
        v[i] = p4[t + i * 256];
        mx = fmaxf(mx, fmaxf(fmaxf(v[i].x, v[i].y), fmaxf(v[i].z, v[i].w)));
    }
    sh[t] = mx; __syncthreads();
    for (int o = 128; o > 0; o >>= 1) { if (t < o) sh[t] = fmaxf(sh[t], sh[t + o]); __syncthreads(); }
    mx = sh[0]; __syncthreads();
    float s = 0.f;
#pragma unroll
    for (int i = 0; i < 4; i++) {
        v[i].x = fexp(v[i].x - mx); v[i].y = fexp(v[i].y - mx);
        v[i].z = fexp(v[i].z - mx); v[i].w = fexp(v[i].w - mx);
        s += v[i].x + v[i].y + v[i].z + v[i].w;
    }
    sh[t] = s; __syncthreads();
    for (int o = 128; o > 0; o >>= 1) { if (t < o) sh[t] += sh[t + o]; __syncthreads(); }
    const float inv = 1.f / sh[0];
    uint2* o2 = reinterpret_cast<uint2*>(g_attn + (size_t)row * MMR);
#pragma unroll
    for (int i = 0; i < 4; i++) {
        __half2 hh[2];
        hh[0] = __floats2half2_rn(v[i].x * inv, v[i].y * inv);
        hh[1] = __floats2half2_rn(v[i].z * inv, v[i].w * inv);
        o2[t + i * 256] = *reinterpret_cast<uint2*>(hh);
    }
}

// ================= split GEMM core (KC=32, 2-stage) — weights (+cvec blocks) =========
#define RSTRIDE 40
#define TILE_HALVES (128 * RSTRIDE)

__device__ __forceinline__ void g2s_h(const __half* __restrict__ g, int ldh,
                                      int row0, int k0, __half* __restrict__ s, int tid) {
#pragma unroll
    for (int j = 0; j < 2; j++) {
        const int idx = j * 256 + tid;
        const int r = idx >> 2, c = idx & 3;
        cp16(smem_u32(s + r * RSTRIDE + c * 8), g + (size_t)(row0 + r) * ldh + k0 + c * 8);
    }
}

__device__ __forceinline__ void hgemm_core_split(
    __half* sm,
    const __half* __restrict__ Ah, const __half* __restrict__ Al,
    const __half* __restrict__ Bh, const __half* __restrict__ Bl,
    __half* __restrict__ Ch, int m0, int n0, int Nq, int Kq) {
    const int tid = threadIdx.x;
    const int lane = tid & 31, warp = tid >> 5;
    const int gq = lane >> 2, cq = lane & 3;
    const int wm = (warp >> 1) * 32, wn = (warp & 1) * 64;
    const int nc = Kq >> 5;

    float acc[2][8][4];
#pragma unroll
    for (int mi = 0; mi < 2; mi++)
#pragma unroll
        for (int ni = 0; ni < 8; ni++)
#pragma unroll
            for (int r = 0; r < 4; r++) acc[mi][ni][r] = 0.f;

    g2s_h(Ah, Kq, m0, 0, sm, tid);
    g2s_h(Bh, Kq, n0, 0, sm + TILE_HALVES, tid);
    g2s_h(Al, Kq, m0, 0, sm + 2 * TILE_HALVES, tid);
    g2s_h(Bl, Kq, n0, 0, sm + 3 * TILE_HALVES, tid);
    CP_COMMIT();

    const uint32_t smb = smem_u32(sm);
    const uint32_t aoff = ((lane & 15) * RSTRIDE + (lane >> 4) * 8) * 2 + wm * 80;
    const uint32_t boff = ((((lane >> 4) << 3) + (lane & 7)) * RSTRIDE +
                           ((lane >> 3) & 1) * 8) * 2 + wn * 80;

    for (int i = 0; i < nc; i++) {
        asm volatile("cp.async.wait_group 0;" ::: "memory");
        __syncthreads();
        if (i + 1 < nc) {
            __half* wb = sm + ((i + 1) & 1) * 4 * TILE_HALVES;
            g2s_h(Ah, Kq, m0, (i + 1) * 32, wb, tid);
            g2s_h(Bh, Kq, n0, (i + 1) * 32, wb + TILE_HALVES, tid);
            g2s_h(Al, Kq, m0, (i + 1) * 32, wb + 2 * TILE_HALVES, tid);
            g2s_h(Bl, Kq, n0, (i + 1) * 32, wb + 3 * TILE_HALVES, tid);
        }
        CP_COMMIT();
        const uint32_t sA  = smb + (i & 1) * 4 * TILE_HALVES * 2;
        const uint32_t sB  = sA + TILE_HALVES * 2;
        const uint32_t sAl = sA + 2 * TILE_HALVES * 2;
        const uint32_t sBl = sA + 3 * TILE_HALVES * 2;
#pragma unroll
        for (int ks = 0; ks < 2; ks++) {
            const uint32_t ko = ks * 32;
            uint32_t a[2][4], al[2][4];
            ldm4(a[0], sA + aoff + ko);
            ldm4(a[1], sA + aoff + 16 * 80 + ko);
            ldm4(al[0], sAl + aoff + ko);
            ldm4(al[1], sAl + aoff + 16 * 80 + ko);
#pragma unroll
            for (int p = 0; p < 4; p++) {
                uint32_t bh4[4], bl4[4];
                ldm4(bh4, sB  + boff + p * 16 * 80 + ko);
                ldm4(bl4, sBl + boff + p * 16 * 80 + ko);
#pragma unroll
                for (int mi = 0; mi < 2; mi++) {
                    mma16(acc[mi][2 * p],     a[mi],  bh4[0], bh4[1]);
                    mma16(acc[mi][2 * p],     a[mi],  bl4[0], bl4[1]);
                    mma16(acc[mi][2 * p],     al[mi], bh4[0], bh4[1]);
                    mma16(acc[mi][2 * p + 1], a[mi],  bh4[2], bh4[3]);
                    mma16(acc[mi][2 * p + 1], a[mi],  bl4[2], bl4[3]);
                    mma16(acc[mi][2 * p + 1], al[mi], bh4[2], bh4[3]);
                }
            }
        }
    }

#pragma unroll
    for (int mi = 0; mi < 2; mi++) {
#pragma unroll
        for (int ni = 0; ni < 8; ni++) {
            const int row = m0 + wm + mi * 16 + gq;
            const int col = n0 + wn + ni * 8 + 2 * cq;
            *reinterpret_cast<__half2*>(Ch + (size_t)row * Nq + col) =
                __floats2half2_rn(acc[mi][ni][0], acc[mi][ni][1]);
            *reinterpret_cast<__half2*>(Ch + (size_t)(row + 8) * Nq + col) =
                __floats2half2_rn(acc[mi][ni][2], acc[mi][ni][3]);
        }
    }
}

__global__ __launch_bounds__(256, 2) void hgemm_weights(const float* __restrict__ bq) {
    extern __shared__ __half sm[];
    const int bx = blockIdx.x;
    if (bx < 256) {          // W2 = mem @ Wq
        hgemm_core_split(sm, g_mhi, g_mlo, g_wqThi, g_wqTlo, g_w2,
                         (bx >> 3) * 128, (bx & 7) * 128, HD, HD);
    } else if (bx < 512) {   // W3T = Wo @ mem^T
        const int b = bx - 256;
        hgemm_core_split(sm, g_wohi, g_wolo, g_mhi, g_mlo, g_w3T,
                         (b >> 5) * 128, (b & 31) * 128, MMR, HD);
    } else {                 // cvec: c[m] = bq . mem[m]
        float* sh = reinterpret_cast<float*>(sm);
        const int m = bx - 512, t = threadIdx.x;
        float s = 0.f;
#pragma unroll
        for (int i = 0; i < 4; i++) {
            const int o = t + i * 256;
            s += bq[o] * (__half2float(g_mhi[(size_t)m * HD + o]) +
                          __half2float(g_mlo[(size_t)m * HD + o]));
        }
        sh[t] = s; __syncthreads();
        for (int o = 128; o > 0; o >>= 1) { if (t < o) sh[t] += sh[t + o]; __syncthreads(); }
        if (t == 0) g_cvec[m] = sh[0];
    }
}

// ========== non-split GEMM (KC=64, 3-stage, 128 thr, 64x64 warp tiles) ================
#define RS64 72
#define T64_HALVES (128 * RS64)
#define STG64_HALVES (2 * T64_HALVES)
#define SMEM64 (3 * STG64_HALVES * 2)    // 110592 B, 3 stages

__device__ __forceinline__ void g2s64(const __half* __restrict__ g, int ldh,
                                      int row0, int k0, __half* __restrict__ s, int tid) {
#pragma unroll
    for (int j = 0; j < 8; j++) {
        const int idx = j * 128 + tid;
        const int r = idx >> 3, c = idx & 7;
        cp16(smem_u32(s + r * RS64 + c * 8), g + (size_t)(row0 + r) * ldh + k0 + c * 8);
    }
}

template <bool BIAS, bool RES>
__global__ __launch_bounds__(128, 2) void hgemm64(
    const __half* __restrict__ Ah, const __half* __restrict__ Bh,
    float* __restrict__ Cf, const float* __restrict__ bias,
    const float* __restrict__ res, int Nq, int Kq) {
    extern __shared__ __half sm[];
    const int tid = threadIdx.x;
    const int lane = tid & 31, warp = tid >> 5;
    const int gq = lane >> 2, cq = lane & 3;
    const int wm = (warp >> 1) * 64, wn = (warp & 1) * 64;
    const int m0 = blockIdx.y * 128, n0 = blockIdx.x * 128;
    const int nc = Kq >> 6;

    float acc[4][8][4];
#pragma unroll
    for (int mi = 0; mi < 4; mi++)
#pragma unroll
        for (int ni = 0; ni < 8; ni++)
#pragma unroll
            for (int r = 0; r < 4; r++) acc[mi][ni][r] = 0.f;

    // prologue: chunks 0,1 -> stages 0,1
#pragma unroll
    for (int p = 0; p < 2; p++) {
        __half* base = sm + p * STG64_HALVES;
        g2s64(Ah, Kq, m0, p * 64, base, tid);
        g2s64(Bh, Kq, n0, p * 64, base + T64_HALVES, tid);
        CP_COMMIT();
    }

    const uint32_t smb = smem_u32(sm);
    const uint32_t aoff = ((lane & 15) * RS64 + (lane >> 4) * 8) * 2 + wm * 144;
    const uint32_t boff = ((((lane >> 4) << 3) + (lane & 7)) * RS64 +
                           ((lane >> 3) & 1) * 8) * 2 + wn * 144;

    for (int i = 0; i < nc; i++) {
        // chunk i resident (FIFO: oldest group completes first); chunk i+1 may fly
        asm volatile("cp.async.wait_group 1;" ::: "memory");
        __syncthreads();
        // issue chunk i+2 into stage (i+2)%3 == (i-1)%3 (consumed last iteration)
        {
            const int ld = i + 2;
            if (ld < nc) {
                __half* wb = sm + (ld % 3) * STG64_HALVES;
                g2s64(Ah, Kq, m0, ld * 64, wb, tid);
                g2s64(Bh, Kq, n0, ld * 64, wb + T64_HALVES, tid);
            }
            CP_COMMIT();   // unconditional: keeps group FIFO uniform
        }
        const uint32_t sA = smb + (i % 3) * STG64_HALVES * 2;
        const uint32_t sB = sA + T64_HALVES * 2;
#pragma unroll
        for (int ks = 0; ks < 4; ks++) {
            const uint32_t ko = ks * 32;
            uint32_t a[4][4];
#pragma unroll
            for (int mi = 0; mi < 4; mi++)
                ldm4(a[mi], sA + aoff + mi * 16 * 144 + ko);
            uint32_t bf[4][4];
#pragma unroll
            for (int p = 0; p < 4; p++)
                ldm4(bf[p], sB + boff + p * 16 * 144 + ko);
#pragma unroll
            for (int p = 0; p < 4; p++)
#pragma unroll
                for (int mi = 0; mi < 4; mi++) {
                    mma16(acc[mi][2 * p],     a[mi], bf[p][0], bf[p][1]);
                    mma16(acc[mi][2 * p + 1], a[mi], bf[p][2], bf[p][3]);
                }
        }
    }

#pragma unroll
    for (int mi = 0; mi < 4; mi++) {
#pragma unroll
        for (int ni = 0; ni < 8; ni++) {
            const int row = m0 + wm + mi * 16 + gq;
            const int col = n0 + wn + ni * 8 + 2 * cq;
            float2 v0 = make_float2(acc[mi][ni][0], acc[mi][ni][1]);
            float2 v1 = make_float2(acc[mi][ni][2], acc[mi][ni][3]);
            if (BIAS) {
                const float2 bb = *reinterpret_cast<const float2*>(bias + col);
                v0.x += bb.x; v0.y += bb.y; v1.x += bb.x; v1.y += bb.y;
            }
            if (RES) {
                const float2 r0 = *reinterpret_cast<const float2*>(res + (size_t)row * Nq + col);
                const float2 r1 = *reinterpret_cast<const float2*>(res + (size_t)(row + 8) * Nq + col);
                v0.x += r0.x; v0.y += r0.y; v1.x += r1.x; v1.y += r1.y;
            }
            *reinterpret_cast<float2*>(Cf + (size_t)row * Nq + col) = v0;
            *reinterpret_cast<float2*>(Cf + (size_t)(row + 8) * Nq + col) = v1;
        }
    }
}

// ---------------- launch -----------------------------------------------------------------
#define SMEM_WTS (2 * 4 * TILE_HALVES * 2)   // 81920

extern "C" void kernel_launch(void* const* d_in, const int* in_sizes, int n_in,
                              void* d_out, int out_size) {
    const float* hidden = (const float*)d_in[0];
    const float* gam    = (const float*)d_in[1];
    const float* bet    = (const float*)d_in[2];
    const float* Wq     = (const float*)d_in[3];
    const float* bq     = (const float*)d_in[4];
    const float* Wo     = (const float*)d_in[5];
    const float* bo     = (const float*)d_in[6];
    const float* memin  = (const float*)d_in[7];
    const float* imp    = (const float*)d_in[8];
    float* out = (float*)d_out;

    __half *p_nhi, *p_w2, *p_w3T, *p_attn;
    float *p_sim, *p_cvec;
    cudaGetSymbolAddress((void**)&p_nhi, g_nhi);
    cudaGetSymbolAddress((void**)&p_w2, g_w2);
    cudaGetSymbolAddress((void**)&p_w3T, g_w3T);
    cudaGetSymbolAddress((void**)&p_attn, g_attn);
    cudaGetSymbolAddress((void**)&p_sim, g_sim);
    cudaGetSymbolAddress((void**)&p_cvec, g_cvec);

    cudaFuncSetAttribute((const void*)hgemm_weights,
                         cudaFuncAttributeMaxDynamicSharedMemorySize, SMEM_WTS);
    cudaFuncSetAttribute((const void*)hgemm64<true, false>,
                         cudaFuncAttributeMaxDynamicSharedMemorySize, SMEM64);
    cudaFuncSetAttribute((const void*)hgemm64<true, true>,
                         cudaFuncAttributeMaxDynamicSharedMemorySize, SMEM64);

    // 1) prep (mem/Wq/Wo splits) + LayerNorm, fused
    prepln_kernel<<<6144 + NR, 256>>>(memin, Wq, Wo, hidden, gam, bet);
    // 2) top-K (both) + scatter
    topk_scatter_kernel<<<1, 1024>>>(imp);
    // 3) weights GEMMs (W2, W3T) + cvec, merged
    hgemm_weights<<<512 + MMR, 256, SMEM_WTS>>>(bq);
    // 4) sim = norm_hi @ W2^T + c                       <- profiled slot
    {
        dim3 g(MMR / 128, NR / 128);
        hgemm64<true, false><<<g, 128, SMEM64>>>(p_nhi, p_w2, p_sim, p_cvec, nullptr, MMR, HD);
    }
    // 5) softmax -> fp16 attn (vectorized)
    softmax_kernel<<<NR, 256>>>();
    // 6) out = attn @ W3T^T + bo + hidden
    {
        dim3 g(HD / 128, NR / 128);
        hgemm64<true, true><<<g, 128, SMEM64>>>(p_attn, p_w3T, out, bo, hidden, HD, MMR);
    }
}

// round 14
// speedup vs baseline: 1.0416x; 1.0416x over previous
#include <cuda_runtime.h>
#include <cuda_fp16.h>
#include <cstdint>
#include <math_constants.h>

#define HD 1024
#define MMR 4096
#define NR 8192
#define TK 64
#define THRESHF 0.5f

// ---------------- scratch globals ---------------------------------------------
__device__ __half g_nhi[(size_t)NR * HD];
__device__ __half g_nlo[(size_t)NR * HD];
__device__ __half g_mhi[(size_t)MMR * HD];
__device__ __half g_mlo[(size_t)MMR * HD];
__device__ __half g_wqThi[(size_t)HD * HD];
__device__ __half g_wqTlo[(size_t)HD * HD];
__device__ __half g_wohi[(size_t)HD * HD];
__device__ __half g_wolo[(size_t)HD * HD];
__device__ __half g_w2[(size_t)MMR * HD];    // mem @ Wq          [MMR, HD]
__device__ __half g_w3T[(size_t)HD * MMR];   // Wo @ mem^T        [HD, MMR]
__device__ __half g_attn[(size_t)NR * MMR];
__device__ float  g_sim[(size_t)NR * MMR];
__device__ float  g_cvec[MMR];
__device__ float  g_surprise[NR];
__device__ int    g_top_idx[TK];
__device__ float  g_top_val[TK];
__device__ int    g_slots[TK];
__device__ float  g_slot_val[TK];

// ---------------- helpers -------------------------------------------------------
__device__ __forceinline__ uint32_t smem_u32(const void* p) {
    uint32_t a;
    asm("{ .reg .u64 t; cvta.to.shared.u64 t, %1; cvt.u32.u64 %0, t; }" : "=r"(a) : "l"(p));
    return a;
}
__device__ __forceinline__ void cp16(uint32_t so, const void* gp) {
    asm volatile("cp.async.cg.shared.global [%0], [%1], 16;" :: "r"(so), "l"(gp) : "memory");
}
#define CP_COMMIT() asm volatile("cp.async.commit_group;" ::: "memory")

__device__ __forceinline__ void mma16(float* d, const uint32_t* a, uint32_t b0, uint32_t b1) {
    asm volatile(
        "mma.sync.aligned.m16n8k16.row.col.f32.f16.f16.f32 "
        "{%0,%1,%2,%3}, {%4,%5,%6,%7}, {%8,%9}, {%0,%1,%2,%3};"
        : "+f"(d[0]), "+f"(d[1]), "+f"(d[2]), "+f"(d[3])
        : "r"(a[0]), "r"(a[1]), "r"(a[2]), "r"(a[3]), "r"(b0), "r"(b1));
}
__device__ __forceinline__ void ldm4(uint32_t* r, uint32_t a) {
    asm volatile("ldmatrix.sync.aligned.m8n8.x4.shared.b16 {%0,%1,%2,%3}, [%4];"
                 : "=r"(r[0]), "=r"(r[1]), "=r"(r[2]), "=r"(r[3]) : "r"(a));
}
__device__ __forceinline__ float fexp(float x) {   // e^x on the FMA pipe
    float t = fmaxf(x * 1.44269504088896340736f, -126.f);
    float n = rintf(t);
    float f = t - n;
    float p = 1.8775767e-3f;
    p = fmaf(p, f, 8.9893397e-3f);
    p = fmaf(p, f, 5.5826318e-2f);
    p = fmaf(p, f, 2.4015361e-1f);
    p = fmaf(p, f, 6.9315308e-1f);
    p = fmaf(p, f, 1.0f);
    return p * __int_as_float(((int)n + 127) << 23);
}
__device__ __forceinline__ void split16(float v, __half& hi, __half& lo) {
    hi = __float2half_rn(v);
    lo = __float2half_rn(v - __half2float(hi));
}

// ---------------- prep + ln fused (one launch) --------------------------------------
__global__ void prepln_kernel(const float* __restrict__ memin,
                              const float* __restrict__ Wq,
                              const float* __restrict__ Wo,
                              const float* __restrict__ x,
                              const float* __restrict__ gam,
                              const float* __restrict__ bet) {
    __shared__ float tile[32][33];
    const int b = blockIdx.x, t = threadIdx.x;
    if (b < 4096) {                       // mem split
        const int i = b * 256 + t;
        const float4 v = reinterpret_cast<const float4*>(memin)[i];
        __half h[4], l[4];
        split16(v.x, h[0], l[0]); split16(v.y, h[1], l[1]);
        split16(v.z, h[2], l[2]); split16(v.w, h[3], l[3]);
        reinterpret_cast<uint2*>(g_mhi)[i] = *reinterpret_cast<uint2*>(h);
        reinterpret_cast<uint2*>(g_mlo)[i] = *reinterpret_cast<uint2*>(l);
        return;
    }
    if (b < 5120) {                       // WqT split (transpose)
        const int tb = b - 4096;
        const int r0 = (tb >> 5) * 32, c0 = (tb & 31) * 32;
        const int tx = t & 31, ty = t >> 5;
#pragma unroll
        for (int k = 0; k < 4; k++)
            tile[ty + k * 8][tx] = Wq[(size_t)(r0 + ty + k * 8) * HD + c0 + tx];
        __syncthreads();
#pragma unroll
        for (int k = 0; k < 4; k++) {
            const size_t o = (size_t)(c0 + ty + k * 8) * HD + r0 + tx;
            split16(tile[tx][ty + k * 8], g_wqThi[o], g_wqTlo[o]);
        }
        return;
    }
    if (b < 6144) {                       // Wo split
        const int i = (b - 5120) * 256 + t;
        const float4 v = reinterpret_cast<const float4*>(Wo)[i];
        __half h[4], l[4];
        split16(v.x, h[0], l[0]); split16(v.y, h[1], l[1]);
        split16(v.z, h[2], l[2]); split16(v.w, h[3], l[3]);
        reinterpret_cast<uint2*>(g_wohi)[i] = *reinterpret_cast<uint2*>(h);
        reinterpret_cast<uint2*>(g_wolo)[i] = *reinterpret_cast<uint2*>(l);
        return;
    }
    // ---- LayerNorm + surprise + fp16 split ----
    __shared__ float sh[256];
    const int row = b - 6144;
    const float* xr = x + (size_t)row * HD;
    float v[4]; float s = 0.f;
#pragma unroll
    for (int i = 0; i < 4; i++) { v[i] = xr[t + i * 256]; s += v[i]; }
    sh[t] = s; __syncthreads();
    for (int o = 128; o > 0; o >>= 1) { if (t < o) sh[t] += sh[t + o]; __syncthreads(); }
    const float mu = sh[0] * (1.f / HD);
    __syncthreads();
    float ss = 0.f;
#pragma unroll
    for (int i = 0; i < 4; i++) { float d = v[i] - mu; ss += d * d; }
    sh[t] = ss; __syncthreads();
    for (int o = 128; o > 0; o >>= 1) { if (t < o) sh[t] += sh[t + o]; __syncthreads(); }
    const float var = sh[0] * (1.f / HD);
    __syncthreads();
    const float inv = rsqrtf(var + 1e-12f);
    float as = 0.f;
#pragma unroll
    for (int i = 0; i < 4; i++) {
        const int c = t + i * 256;
        const float y = (v[i] - mu) * inv * gam[c] + bet[c];
        split16(y, g_nhi[(size_t)row * HD + c], g_nlo[(size_t)row * HD + c]);
        as += fabsf(y);
    }
    sh[t] = as; __syncthreads();
    for (int o = 128; o > 0; o >>= 1) { if (t < o) sh[t] += sh[t + o]; __syncthreads(); }
    if (t == 0) g_surprise[row] = sh[0] * (1.f / HD);
}

// ---------------- top-K: two selections run CONCURRENTLY in half-blocks ---------------
__device__ __forceinline__ void argmax_shfl(float& v, int& i) {
#pragma unroll
    for (int o = 16; o > 0; o >>= 1) {
        const float ov = __shfl_down_sync(0xffffffffu, v, o);
        const int   oi = __shfl_down_sync(0xffffffffu, i, o);
        if (ov > v || (ov == v && oi < i)) { v = ov; i = oi; }
    }
}
#define BARH(id) asm volatile("bar.sync %0, 512;" :: "r"(id) : "memory")

template <int PER, bool NEG>
__device__ void topk_group(const float* __restrict__ src,
                           int* __restrict__ oidx, float* __restrict__ oval,
                           float* svv, int* svi, float* swv, int* swi, int barid) {
    const int gt = threadIdx.x & 511;         // 0..511 within the half-block
    const int lane = gt & 31, w = gt >> 5;     // 16 warps per half
    float loc[PER];
#pragma unroll
    for (int i = 0; i < PER; i++) { float x = src[gt * PER + i]; loc[i] = NEG ? -x : x; }
    for (int k = 0; k < TK; k++) {
        float bv = -CUDART_INF_F; int bi = 0x7fffffff;
#pragma unroll
        for (int i = 0; i < PER; i++)
            if (loc[i] > bv) { bv = loc[i]; bi = gt * PER + i; }
        argmax_shfl(bv, bi);
        if (lane == 0) { svv[w] = bv; svi[w] = bi; }
        BARH(barid);
        if (w == 0) {
            float v2 = (lane < 16) ? svv[lane] : -CUDART_INF_F;
            int   i2 = (lane < 16) ? svi[lane] : 0x7fffffff;
            argmax_shfl(v2, i2);
            if (lane == 0) {
                *swv = v2; *swi = i2;
                oidx[k] = i2; oval[k] = NEG ? -v2 : v2;
            }
        }
        BARH(barid);
        const int win = *swi;
        const int rel = win - gt * PER;
        if ((unsigned)rel < (unsigned)PER) loc[rel] = -CUDART_INF_F;
    }
}
__global__ void topk_scatter_kernel(const float* __restrict__ imp) {
    __shared__ float svv[2][16]; __shared__ int svi[2][16];
    __shared__ float swv[2];     __shared__ int swi[2];
    const int t = threadIdx.x;
    if (t < 512)
        topk_group<NR / 512, false>(g_surprise, g_top_idx, g_top_val,
                                    svv[0], svi[0], &swv[0], &swi[0], 1);
    else
        topk_group<MMR / 512, true>(imp, g_slots, g_slot_val,
                                    svv[1], svi[1], &swv[1], &swi[1], 2);
    __syncthreads();
    for (int idx = t; idx < TK * 256; idx += 1024) {
        const int j = idx >> 8, e = idx & 255;
        if (g_top_val[j] > THRESHF) {
            const int src = g_top_idx[j], dst = g_slots[j];
            reinterpret_cast<uint2*>(g_mhi + (size_t)dst * HD)[e] =
                reinterpret_cast<const uint2*>(g_nhi + (size_t)src * HD)[e];
            reinterpret_cast<uint2*>(g_mlo + (size_t)dst * HD)[e] =
                reinterpret_cast<const uint2*>(g_nlo + (size_t)src * HD)[e];
        }
    }
}

// ---------------- softmax: g_sim (fp32, float4) -> g_attn (fp16) ----------------------
__global__ void softmax_kernel() {
    __shared__ float sh[256];
    const int row = blockIdx.x, t = threadIdx.x;
    const float4* p4 = reinterpret_cast<const float4*>(g_sim + (size_t)row * MMR);
    float4 v[4];
    float mx = -CUDART_INF_F;
#pragma unroll
    for (int i = 0; i < 4; i++) {
        v[i] = p4[t + i * 256];
        mx = fmaxf(mx, fmaxf(fmaxf(v[i].x, v[i].y), fmaxf(v[i].z, v[i].w)));
    }
    sh[t] = mx; __syncthreads();
    for (int o = 128; o > 0; o >>= 1) { if (t < o) sh[t] = fmaxf(sh[t], sh[t + o]); __syncthreads(); }
    mx = sh[0]; __syncthreads();
    float s = 0.f;
#pragma unroll
    for (int i = 0; i < 4; i++) {
        v[i].x = fexp(v[i].x - mx); v[i].y = fexp(v[i].y - mx);
        v[i].z = fexp(v[i].z - mx); v[i].w = fexp(v[i].w - mx);
        s += v[i].x + v[i].y + v[i].z + v[i].w;
    }
    sh[t] = s; __syncthreads();
    for (int o = 128; o > 0; o >>= 1) { if (t < o) sh[t] += sh[t + o]; __syncthreads(); }
    const float inv = 1.f / sh[0];
    uint2* o2 = reinterpret_cast<uint2*>(g_attn + (size_t)row * MMR);
#pragma unroll
    for (int i = 0; i < 4; i++) {
        __half2 hh[2];
        hh[0] = __floats2half2_rn(v[i].x * inv, v[i].y * inv);
        hh[1] = __floats2half2_rn(v[i].z * inv, v[i].w * inv);
        o2[t + i * 256] = *reinterpret_cast<uint2*>(hh);
    }
}

// ========= split GEMM core (KC=32, 2-stage, 128 thr, 64x64 warp tiles) ================
#define RSTRIDE 40
#define TILE_HALVES (128 * RSTRIDE)

__device__ __forceinline__ void g2s_h128(const __half* __restrict__ g, int ldh,
                                         int row0, int k0, __half* __restrict__ s, int tid) {
#pragma unroll
    for (int j = 0; j < 4; j++) {
        const int idx = j * 128 + tid;
        const int r = idx >> 2, c = idx & 3;
        cp16(smem_u32(s + r * RSTRIDE + c * 8), g + (size_t)(row0 + r) * ldh + k0 + c * 8);
    }
}

__device__ __forceinline__ void hgemm_core_split(
    __half* sm,
    const __half* __restrict__ Ah, const __half* __restrict__ Al,
    const __half* __restrict__ Bh, const __half* __restrict__ Bl,
    __half* __restrict__ Ch, int m0, int n0, int Nq, int Kq) {
    const int tid = threadIdx.x;
    const int lane = tid & 31, warp = tid >> 5;
    const int gq = lane >> 2, cq = lane & 3;
    const int wm = (warp >> 1) * 64, wn = (warp & 1) * 64;
    const int nc = Kq >> 5;

    float acc[4][8][4];
#pragma unroll
    for (int mi = 0; mi < 4; mi++)
#pragma unroll
        for (int ni = 0; ni < 8; ni++)
#pragma unroll
            for (int r = 0; r < 4; r++) acc[mi][ni][r] = 0.f;

    g2s_h128(Ah, Kq, m0, 0, sm, tid);
    g2s_h128(Bh, Kq, n0, 0, sm + TILE_HALVES, tid);
    g2s_h128(Al, Kq, m0, 0, sm + 2 * TILE_HALVES, tid);
    g2s_h128(Bl, Kq, n0, 0, sm + 3 * TILE_HALVES, tid);
    CP_COMMIT();

    const uint32_t smb = smem_u32(sm);
    const uint32_t aoff = ((lane & 15) * RSTRIDE + (lane >> 4) * 8) * 2 + wm * 80;
    const uint32_t boff = ((((lane >> 4) << 3) + (lane & 7)) * RSTRIDE +
                           ((lane >> 3) & 1) * 8) * 2 + wn * 80;

    for (int i = 0; i < nc; i++) {
        asm volatile("cp.async.wait_group 0;" ::: "memory");
        __syncthreads();
        if (i + 1 < nc) {
            __half* wb = sm + ((i + 1) & 1) * 4 * TILE_HALVES;
            g2s_h128(Ah, Kq, m0, (i + 1) * 32, wb, tid);
            g2s_h128(Bh, Kq, n0, (i + 1) * 32, wb + TILE_HALVES, tid);
            g2s_h128(Al, Kq, m0, (i + 1) * 32, wb + 2 * TILE_HALVES, tid);
            g2s_h128(Bl, Kq, n0, (i + 1) * 32, wb + 3 * TILE_HALVES, tid);
        }
        CP_COMMIT();
        const uint32_t sA  = smb + (i & 1) * 4 * TILE_HALVES * 2;
        const uint32_t sB  = sA + TILE_HALVES * 2;
        const uint32_t sAl = sA + 2 * TILE_HALVES * 2;
        const uint32_t sBl = sA + 3 * TILE_HALVES * 2;
#pragma unroll
        for (int ks = 0; ks < 2; ks++) {
            const uint32_t ko = ks * 32;
            uint32_t a[4][4], al[4][4];
#pragma unroll
            for (int mi = 0; mi < 4; mi++) {
                ldm4(a[mi],  sA  + aoff + mi * 16 * 80 + ko);
                ldm4(al[mi], sAl + aoff + mi * 16 * 80 + ko);
            }
#pragma unroll
            for (int p = 0; p < 4; p++) {
                uint32_t bh4[4], bl4[4];
                ldm4(bh4, sB  + boff + p * 16 * 80 + ko);
                ldm4(bl4, sBl + boff + p * 16 * 80 + ko);
#pragma unroll
                for (int mi = 0; mi < 4; mi++) {
                    mma16(acc[mi][2 * p],     a[mi],  bh4[0], bh4[1]);
                    mma16(acc[mi][2 * p],     a[mi],  bl4[0], bl4[1]);
                    mma16(acc[mi][2 * p],     al[mi], bh4[0], bh4[1]);
                    mma16(acc[mi][2 * p + 1], a[mi],  bh4[2], bh4[3]);
                    mma16(acc[mi][2 * p + 1], a[mi],  bl4[2], bl4[3]);
                    mma16(acc[mi][2 * p + 1], al[mi], bh4[2], bh4[3]);
                }
            }
        }
    }

#pragma unroll
    for (int mi = 0; mi < 4; mi++) {
#pragma unroll
        for (int ni = 0; ni < 8; ni++) {
            const int row = m0 + wm + mi * 16 + gq;
            const int col = n0 + wn + ni * 8 + 2 * cq;
            *reinterpret_cast<__half2*>(Ch + (size_t)row * Nq + col) =
                __floats2half2_rn(acc[mi][ni][0], acc[mi][ni][1]);
            *reinterpret_cast<__half2*>(Ch + (size_t)(row + 8) * Nq + col) =
                __floats2half2_rn(acc[mi][ni][2], acc[mi][ni][3]);
        }
    }
}

__global__ __launch_bounds__(128, 2) void hgemm_weights(const float* __restrict__ bq) {
    extern __shared__ __half sm[];
    const int bx = blockIdx.x;
    if (bx < 256) {          // W2 = mem @ Wq
        hgemm_core_split(sm, g_mhi, g_mlo, g_wqThi, g_wqTlo, g_w2,
                         (bx >> 3) * 128, (bx & 7) * 128, HD, HD);
    } else if (bx < 512) {   // W3T = Wo @ mem^T
        const int b = bx - 256;
        hgemm_core_split(sm, g_wohi, g_wolo, g_mhi, g_mlo, g_w3T,
                         (b >> 5) * 128, (b & 31) * 128, MMR, HD);
    } else {                 // cvec: c[m] = bq . mem[m]  (128 thr x 8 elems)
        float* sh = reinterpret_cast<float*>(sm);
        const int m = bx - 512, t = threadIdx.x;
        float s = 0.f;
#pragma unroll
        for (int i = 0; i < 8; i++) {
            const int o = t + i * 128;
            s += bq[o] * (__half2float(g_mhi[(size_t)m * HD + o]) +
                          __half2float(g_mlo[(size_t)m * HD + o]));
        }
        sh[t] = s; __syncthreads();
        for (int o = 64; o > 0; o >>= 1) { if (t < o) sh[t] += sh[t + o]; __syncthreads(); }
        if (t == 0) g_cvec[m] = sh[0];
    }
}

// ========== non-split GEMM (KC=64, 3-stage, 128 thr, 64x64 warp tiles) ================
#define RS64 72
#define T64_HALVES (128 * RS64)
#define STG64_HALVES (2 * T64_HALVES)
#define SMEM64 (3 * STG64_HALVES * 2)    // 110592 B, 3 stages

__device__ __forceinline__ void g2s64(const __half* __restrict__ g, int ldh,
                                      int row0, int k0, __half* __restrict__ s, int tid) {
#pragma unroll
    for (int j = 0; j < 8; j++) {
        const int idx = j * 128 + tid;
        const int r = idx >> 3, c = idx & 7;
        cp16(smem_u32(s + r * RS64 + c * 8), g + (size_t)(row0 + r) * ldh + k0 + c * 8);
    }
}

template <bool BIAS, bool RES>
__global__ __launch_bounds__(128, 2) void hgemm64(
    const __half* __restrict__ Ah, const __half* __restrict__ Bh,
    float* __restrict__ Cf, const float* __restrict__ bias,
    const float* __restrict__ res, int Nq, int Kq) {
    extern __shared__ __half sm[];
    const int tid = threadIdx.x;
    const int lane = tid & 31, warp = tid >> 5;
    const int gq = lane >> 2, cq = lane & 3;
    const int wm = (warp >> 1) * 64, wn = (warp & 1) * 64;
    const int m0 = blockIdx.y * 128, n0 = blockIdx.x * 128;
    const int nc = Kq >> 6;

    float acc[4][8][4];
#pragma unroll
    for (int mi = 0; mi < 4; mi++)
#pragma unroll
        for (int ni = 0; ni < 8; ni++)
#pragma unroll
            for (int r = 0; r < 4; r++) acc[mi][ni][r] = 0.f;

#pragma unroll
    for (int p = 0; p < 2; p++) {
        __half* base = sm + p * STG64_HALVES;
        g2s64(Ah, Kq, m0, p * 64, base, tid);
        g2s64(Bh, Kq, n0, p * 64, base + T64_HALVES, tid);
        CP_COMMIT();
    }

    const uint32_t smb = smem_u32(sm);
    const uint32_t aoff = ((lane & 15) * RS64 + (lane >> 4) * 8) * 2 + wm * 144;
    const uint32_t boff = ((((lane >> 4) << 3) + (lane & 7)) * RS64 +
                           ((lane >> 3) & 1) * 8) * 2 + wn * 144;

    for (int i = 0; i < nc; i++) {
        asm volatile("cp.async.wait_group 1;" ::: "memory");
        __syncthreads();
        {
            const int ld = i + 2;
            if (ld < nc) {
                __half* wb = sm + (ld % 3) * STG64_HALVES;
                g2s64(Ah, Kq, m0, ld * 64, wb, tid);
                g2s64(Bh, Kq, n0, ld * 64, wb + T64_HALVES, tid);
            }
            CP_COMMIT();
        }
        const uint32_t sA = smb + (i % 3) * STG64_HALVES * 2;
        const uint32_t sB = sA + T64_HALVES * 2;
#pragma unroll
        for (int ks = 0; ks < 4; ks++) {
            const uint32_t ko = ks * 32;
            uint32_t a[4][4];
#pragma unroll
            for (int mi = 0; mi < 4; mi++)
                ldm4(a[mi], sA + aoff + mi * 16 * 144 + ko);
            uint32_t bf[4][4];
#pragma unroll
            for (int p = 0; p < 4; p++)
                ldm4(bf[p], sB + boff + p * 16 * 144 + ko);
#pragma unroll
            for (int p = 0; p < 4; p++)
#pragma unroll
                for (int mi = 0; mi < 4; mi++) {
                    mma16(acc[mi][2 * p],     a[mi], bf[p][0], bf[p][1]);
                    mma16(acc[mi][2 * p + 1], a[mi], bf[p][2], bf[p][3]);
                }
        }
    }

#pragma unroll
    for (int mi = 0; mi < 4; mi++) {
#pragma unroll
        for (int ni = 0; ni < 8; ni++) {
            const int row = m0 + wm + mi * 16 + gq;
            const int col = n0 + wn + ni * 8 + 2 * cq;
            float2 v0 = make_float2(acc[mi][ni][0], acc[mi][ni][1]);
            float2 v1 = make_float2(acc[mi][ni][2], acc[mi][ni][3]);
            if (BIAS) {
                const float2 bb = *reinterpret_cast<const float2*>(bias + col);
                v0.x += bb.x; v0.y += bb.y; v1.x += bb.x; v1.y += bb.y;
            }
            if (RES) {
                const float2 r0 = *reinterpret_cast<const float2*>(res + (size_t)row * Nq + col);
                const float2 r1 = *reinterpret_cast<const float2*>(res + (size_t)(row + 8) * Nq + col);
                v0.x += r0.x; v0.y += r0.y; v1.x += r1.x; v1.y += r1.y;
            }
            *reinterpret_cast<float2*>(Cf + (size_t)row * Nq + col) = v0;
            *reinterpret_cast<float2*>(Cf + (size_t)(row + 8) * Nq + col) = v1;
        }
    }
}

// ---------------- launch -----------------------------------------------------------------
#define SMEM_WTS (2 * 4 * TILE_HALVES * 2)   // 81920

extern "C" void kernel_launch(void* const* d_in, const int* in_sizes, int n_in,
                              void* d_out, int out_size) {
    const float* hidden = (const float*)d_in[0];
    const float* gam    = (const float*)d_in[1];
    const float* bet    = (const float*)d_in[2];
    const float* Wq     = (const float*)d_in[3];
    const float* bq     = (const float*)d_in[4];
    const float* Wo     = (const float*)d_in[5];
    const float* bo     = (const float*)d_in[6];
    const float* memin  = (const float*)d_in[7];
    const float* imp    = (const float*)d_in[8];
    float* out = (float*)d_out;

    __half *p_nhi, *p_w2, *p_w3T, *p_attn;
    float *p_sim, *p_cvec;
    cudaGetSymbolAddress((void**)&p_nhi, g_nhi);
    cudaGetSymbolAddress((void**)&p_w2, g_w2);
    cudaGetSymbolAddress((void**)&p_w3T, g_w3T);
    cudaGetSymbolAddress((void**)&p_attn, g_attn);
    cudaGetSymbolAddress((void**)&p_sim, g_sim);
    cudaGetSymbolAddress((void**)&p_cvec, g_cvec);

    cudaFuncSetAttribute((const void*)hgemm_weights,
                         cudaFuncAttributeMaxDynamicSharedMemorySize, SMEM_WTS);
    cudaFuncSetAttribute((const void*)hgemm64<true, false>,
                         cudaFuncAttributeMaxDynamicSharedMemorySize, SMEM64);
    cudaFuncSetAttribute((const void*)hgemm64<true, true>,
                         cudaFuncAttributeMaxDynamicSharedMemorySize, SMEM64);

    // 1) prep (mem/Wq/Wo splits) + LayerNorm, fused
    prepln_kernel<<<6144 + NR, 256>>>(memin, Wq, Wo, hidden, gam, bet);
    // 2) both top-K selections concurrently (half-blocks) + scatter
    topk_scatter_kernel<<<1, 1024>>>(imp);
    // 3) weights GEMMs (W2, W3T) + cvec, merged (64x64 warp-tile split core)
    hgemm_weights<<<512 + MMR, 128, SMEM_WTS>>>(bq);
    // 4) sim = norm_hi @ W2^T + c                       <- profiled slot
    {
        dim3 g(MMR / 128, NR / 128);
        hgemm64<true, false><<<g, 128, SMEM64>>>(p_nhi, p_w2, p_sim, p_cvec, nullptr, MMR, HD);
    }
    // 5) softmax -> fp16 attn (vectorized)
    softmax_kernel<<<NR, 256>>>();
    // 6) out = attn @ W3T^T + bo + hidden
    {
        dim3 g(HD / 128, NR / 128);
        hgemm64<true, true><<<g, 128, SMEM64>>>(p_attn, p_w3T, out, bo, hidden, HD, MMR);
    }
}

// round 16
// speedup vs baseline: 1.0445x; 1.0028x over previous
#include <cuda_runtime.h>
#include <cuda_fp16.h>
#include <cstdint>
#include <math_constants.h>

#define HD 1024
#define MMR 4096
#define NR 8192
#define TK 64
#define THRESHF 0.5f

// ---------------- scratch globals ---------------------------------------------
__device__ __half g_nhi[(size_t)NR * HD];
__device__ __half g_nlo[(size_t)NR * HD];
__device__ __half g_mhi[(size_t)MMR * HD];
__device__ __half g_mlo[(size_t)MMR * HD];
__device__ __half g_wqThi[(size_t)HD * HD];
__device__ __half g_wqTlo[(size_t)HD * HD];
__device__ __half g_wohi[(size_t)HD * HD];
__device__ __half g_wolo[(size_t)HD * HD];
__device__ __half g_w2[(size_t)MMR * HD];    // mem @ Wq          [MMR, HD]
__device__ __half g_w3T[(size_t)HD * MMR];   // Wo @ mem^T        [HD, MMR]
__device__ __half g_attn[(size_t)NR * MMR];
__device__ float  g_sim[(size_t)NR * MMR];
__device__ float  g_cvec[MMR];
__device__ float  g_surprise[NR];
__device__ int    g_top_idx[TK];
__device__ float  g_top_val[TK];
__device__ int    g_slots[TK];
__device__ float  g_slot_val[TK];

// ---------------- helpers -------------------------------------------------------
__device__ __forceinline__ uint32_t smem_u32(const void* p) {
    uint32_t a;
    asm("{ .reg .u64 t; cvta.to.shared.u64 t, %1; cvt.u32.u64 %0, t; }" : "=r"(a) : "l"(p));
    return a;
}
__device__ __forceinline__ void cp16(uint32_t so, const void* gp) {
    asm volatile("cp.async.cg.shared.global [%0], [%1], 16;" :: "r"(so), "l"(gp) : "memory");
}
#define CP_COMMIT() asm volatile("cp.async.commit_group;" ::: "memory")

__device__ __forceinline__ void mma16(float* d, const uint32_t* a, uint32_t b0, uint32_t b1) {
    asm volatile(
        "mma.sync.aligned.m16n8k16.row.col.f32.f16.f16.f32 "
        "{%0,%1,%2,%3}, {%4,%5,%6,%7}, {%8,%9}, {%0,%1,%2,%3};"
        : "+f"(d[0]), "+f"(d[1]), "+f"(d[2]), "+f"(d[3])
        : "r"(a[0]), "r"(a[1]), "r"(a[2]), "r"(a[3]), "r"(b0), "r"(b1));
}
__device__ __forceinline__ void ldm4(uint32_t* r, uint32_t a) {
    asm volatile("ldmatrix.sync.aligned.m8n8.x4.shared.b16 {%0,%1,%2,%3}, [%4];"
                 : "=r"(r[0]), "=r"(r[1]), "=r"(r[2]), "=r"(r[3]) : "r"(a));
}
__device__ __forceinline__ float fexp(float x) {   // e^x on the FMA pipe
    float t = fmaxf(x * 1.44269504088896340736f, -126.f);
    float n = rintf(t);
    float f = t - n;
    float p = 1.8775767e-3f;
    p = fmaf(p, f, 8.9893397e-3f);
    p = fmaf(p, f, 5.5826318e-2f);
    p = fmaf(p, f, 2.4015361e-1f);
    p = fmaf(p, f, 6.9315308e-1f);
    p = fmaf(p, f, 1.0f);
    return p * __int_as_float(((int)n + 127) << 23);
}
__device__ __forceinline__ void split16(float v, __half& hi, __half& lo) {
    hi = __float2half_rn(v);
    lo = __float2half_rn(v - __half2float(hi));
}

// ---------------- prep + ln fused (one launch) --------------------------------------
__global__ void prepln_kernel(const float* __restrict__ memin,
                              const float* __restrict__ Wq,
                              const float* __restrict__ Wo,
                              const float* __restrict__ x,
                              const float* __restrict__ gam,
                              const float* __restrict__ bet) {
    __shared__ float tile[32][33];
    const int b = blockIdx.x, t = threadIdx.x;
    if (b < 4096) {                       // mem split
        const int i = b * 256 + t;
        const float4 v = reinterpret_cast<const float4*>(memin)[i];
        __half h[4], l[4];
        split16(v.x, h[0], l[0]); split16(v.y, h[1], l[1]);
        split16(v.z, h[2], l[2]); split16(v.w, h[3], l[3]);
        reinterpret_cast<uint2*>(g_mhi)[i] = *reinterpret_cast<uint2*>(h);
        reinterpret_cast<uint2*>(g_mlo)[i] = *reinterpret_cast<uint2*>(l);
        return;
    }
    if (b < 5120) {                       // WqT split (transpose)
        const int tb = b - 4096;
        const int r0 = (tb >> 5) * 32, c0 = (tb & 31) * 32;
        const int tx = t & 31, ty = t >> 5;
#pragma unroll
        for (int k = 0; k < 4; k++)
            tile[ty + k * 8][tx] = Wq[(size_t)(r0 + ty + k * 8) * HD + c0 + tx];
        __syncthreads();
#pragma unroll
        for (int k = 0; k < 4; k++) {
            const size_t o = (size_t)(c0 + ty + k * 8) * HD + r0 + tx;
            split16(tile[tx][ty + k * 8], g_wqThi[o], g_wqTlo[o]);
        }
        return;
    }
    if (b < 6144) {                       // Wo split
        const int i = (b - 5120) * 256 + t;
        const float4 v = reinterpret_cast<const float4*>(Wo)[i];
        __half h[4], l[4];
        split16(v.x, h[0], l[0]); split16(v.y, h[1], l[1]);
        split16(v.z, h[2], l[2]); split16(v.w, h[3], l[3]);
        reinterpret_cast<uint2*>(g_wohi)[i] = *reinterpret_cast<uint2*>(h);
        reinterpret_cast<uint2*>(g_wolo)[i] = *reinterpret_cast<uint2*>(l);
        return;
    }
    // ---- LayerNorm + surprise + fp16 split ----
    __shared__ float sh[256];
    const int row = b - 6144;
    const float* xr = x + (size_t)row * HD;
    float v[4]; float s = 0.f;
#pragma unroll
    for (int i = 0; i < 4; i++) { v[i] = xr[t + i * 256]; s += v[i]; }
    sh[t] = s; __syncthreads();
    for (int o = 128; o > 0; o >>= 1) { if (t < o) sh[t] += sh[t + o]; __syncthreads(); }
    const float mu = sh[0] * (1.f / HD);
    __syncthreads();
    float ss = 0.f;
#pragma unroll
    for (int i = 0; i < 4; i++) { float d = v[i] - mu; ss += d * d; }
    sh[t] = ss; __syncthreads();
    for (int o = 128; o > 0; o >>= 1) { if (t < o) sh[t] += sh[t + o]; __syncthreads(); }
    const float var = sh[0] * (1.f / HD);
    __syncthreads();
    const float inv = rsqrtf(var + 1e-12f);
    float as = 0.f;
#pragma unroll
    for (int i = 0; i < 4; i++) {
        const int c = t + i * 256;
        const float y = (v[i] - mu) * inv * gam[c] + bet[c];
        split16(y, g_nhi[(size_t)row * HD + c], g_nlo[(size_t)row * HD + c]);
        as += fabsf(y);
    }
    sh[t] = as; __syncthreads();
    for (int o = 128; o > 0; o >>= 1) { if (t < o) sh[t] += sh[t + o]; __syncthreads(); }
    if (t == 0) g_surprise[row] = sh[0] * (1.f / HD);
}

// ---------------- top-K: two selections run CONCURRENTLY in half-blocks ---------------
__device__ __forceinline__ void argmax_shfl(float& v, int& i) {
#pragma unroll
    for (int o = 16; o > 0; o >>= 1) {
        const float ov = __shfl_down_sync(0xffffffffu, v, o);
        const int   oi = __shfl_down_sync(0xffffffffu, i, o);
        if (ov > v || (ov == v && oi < i)) { v = ov; i = oi; }
    }
}
#define BARH(id) asm volatile("bar.sync %0, 512;" :: "r"(id) : "memory")

template <int PER, bool NEG>
__device__ void topk_group(const float* __restrict__ src,
                           int* __restrict__ oidx, float* __restrict__ oval,
                           float* svv, int* svi, float* swv, int* swi, int barid) {
    const int gt = threadIdx.x & 511;         // 0..511 within the half-block
    const int lane = gt & 31, w = gt >> 5;     // 16 warps per half
    float loc[PER];
#pragma unroll
    for (int i = 0; i < PER; i++) { float x = src[gt * PER + i]; loc[i] = NEG ? -x : x; }
    for (int k = 0; k < TK; k++) {
        float bv = -CUDART_INF_F; int bi = 0x7fffffff;
#pragma unroll
        for (int i = 0; i < PER; i++)
            if (loc[i] > bv) { bv = loc[i]; bi = gt * PER + i; }
        argmax_shfl(bv, bi);
        if (lane == 0) { svv[w] = bv; svi[w] = bi; }
        BARH(barid);
        if (w == 0) {
            float v2 = (lane < 16) ? svv[lane] : -CUDART_INF_F;
            int   i2 = (lane < 16) ? svi[lane] : 0x7fffffff;
            argmax_shfl(v2, i2);
            if (lane == 0) {
                *swv = v2; *swi = i2;
                oidx[k] = i2; oval[k] = NEG ? -v2 : v2;
            }
        }
        BARH(barid);
        const int win = *swi;
        const int rel = win - gt * PER;
        if ((unsigned)rel < (unsigned)PER) loc[rel] = -CUDART_INF_F;
    }
}
__global__ void topk_scatter_kernel(const float* __restrict__ imp) {
    __shared__ float svv[2][16]; __shared__ int svi[2][16];
    __shared__ float swv[2];     __shared__ int swi[2];
    const int t = threadIdx.x;
    if (t < 512)
        topk_group<NR / 512, false>(g_surprise, g_top_idx, g_top_val,
                                    svv[0], svi[0], &swv[0], &swi[0], 1);
    else
        topk_group<MMR / 512, true>(imp, g_slots, g_slot_val,
                                    svv[1], svi[1], &swv[1], &swi[1], 2);
    __syncthreads();
    for (int idx = t; idx < TK * 256; idx += 1024) {
        const int j = idx >> 8, e = idx & 255;
        if (g_top_val[j] > THRESHF) {
            const int src = g_top_idx[j], dst = g_slots[j];
            reinterpret_cast<uint2*>(g_mhi + (size_t)dst * HD)[e] =
                reinterpret_cast<const uint2*>(g_nhi + (size_t)src * HD)[e];
            reinterpret_cast<uint2*>(g_mlo + (size_t)dst * HD)[e] =
                reinterpret_cast<const uint2*>(g_nlo + (size_t)src * HD)[e];
        }
    }
}

// ------- softmax: block-per-row (4096 cols = 256 thr x 4 float4), 2 barriers ----------
__global__ __launch_bounds__(256) void softmax_kernel() {
    __shared__ float sh[8];
    const int row = blockIdx.x, t = threadIdx.x;
    const int lane = t & 31, w = t >> 5;
    const float4* p4 = reinterpret_cast<const float4*>(g_sim + (size_t)row * MMR);
    float4 v[4];
    float mx = -CUDART_INF_F;
#pragma unroll
    for (int i = 0; i < 4; i++) {
        v[i] = p4[t + i * 256];
        mx = fmaxf(mx, fmaxf(fmaxf(v[i].x, v[i].y), fmaxf(v[i].z, v[i].w)));
    }
#pragma unroll
    for (int o = 16; o > 0; o >>= 1)
        mx = fmaxf(mx, __shfl_xor_sync(0xffffffffu, mx, o));
    if (lane == 0) sh[w] = mx;
    __syncthreads();
#pragma unroll
    for (int i = 0; i < 8; i++) mx = fmaxf(mx, sh[i]);

    float s = 0.f;
#pragma unroll
    for (int i = 0; i < 4; i++) {
        v[i].x = fexp(v[i].x - mx); v[i].y = fexp(v[i].y - mx);
        v[i].z = fexp(v[i].z - mx); v[i].w = fexp(v[i].w - mx);
        s += v[i].x + v[i].y + v[i].z + v[i].w;
    }
#pragma unroll
    for (int o = 16; o > 0; o >>= 1)
        s += __shfl_xor_sync(0xffffffffu, s, o);
    __syncthreads();   // sh reuse: all warps done reading max values
    if (lane == 0) sh[w] = s;
    __syncthreads();
    s = 0.f;
#pragma unroll
    for (int i = 0; i < 8; i++) s += sh[i];

    const float inv = 1.f / s;
    uint2* o2 = reinterpret_cast<uint2*>(g_attn + (size_t)row * MMR);
#pragma unroll
    for (int i = 0; i < 4; i++) {
        __half2 hh[2];
        hh[0] = __floats2half2_rn(v[i].x * inv, v[i].y * inv);
        hh[1] = __floats2half2_rn(v[i].z * inv, v[i].w * inv);
        o2[t + i * 256] = *reinterpret_cast<uint2*>(hh);
    }
}

// ========= split GEMM core (KC=32, 2-stage, 128 thr, 64x64 warp tiles) ================
#define RSTRIDE 40
#define TILE_HALVES (128 * RSTRIDE)

__device__ __forceinline__ void g2s_h128(const __half* __restrict__ g, int ldh,
                                         int row0, int k0, __half* __restrict__ s, int tid) {
#pragma unroll
    for (int j = 0; j < 4; j++) {
        const int idx = j * 128 + tid;
        const int r = idx >> 2, c = idx & 3;
        cp16(smem_u32(s + r * RSTRIDE + c * 8), g + (size_t)(row0 + r) * ldh + k0 + c * 8);
    }
}

__device__ __forceinline__ void hgemm_core_split(
    __half* sm,
    const __half* __restrict__ Ah, const __half* __restrict__ Al,
    const __half* __restrict__ Bh, const __half* __restrict__ Bl,
    __half* __restrict__ Ch, int m0, int n0, int Nq, int Kq) {
    const int tid = threadIdx.x;
    const int lane = tid & 31, warp = tid >> 5;
    const int gq = lane >> 2, cq = lane & 3;
    const int wm = (warp >> 1) * 64, wn = (warp & 1) * 64;
    const int nc = Kq >> 5;

    float acc[4][8][4];
#pragma unroll
    for (int mi = 0; mi < 4; mi++)
#pragma unroll
        for (int ni = 0; ni < 8; ni++)
#pragma unroll
            for (int r = 0; r < 4; r++) acc[mi][ni][r] = 0.f;

    g2s_h128(Ah, Kq, m0, 0, sm, tid);
    g2s_h128(Bh, Kq, n0, 0, sm + TILE_HALVES, tid);
    g2s_h128(Al, Kq, m0, 0, sm + 2 * TILE_HALVES, tid);
    g2s_h128(Bl, Kq, n0, 0, sm + 3 * TILE_HALVES, tid);
    CP_COMMIT();

    const uint32_t smb = smem_u32(sm);
    const uint32_t aoff = ((lane & 15) * RSTRIDE + (lane >> 4) * 8) * 2 + wm * 80;
    const uint32_t boff = ((((lane >> 4) << 3) + (lane & 7)) * RSTRIDE +
                           ((lane >> 3) & 1) * 8) * 2 + wn * 80;

    for (int i = 0; i < nc; i++) {
        asm volatile("cp.async.wait_group 0;" ::: "memory");
        __syncthreads();
        if (i + 1 < nc) {
            __half* wb = sm + ((i + 1) & 1) * 4 * TILE_HALVES;
            g2s_h128(Ah, Kq, m0, (i + 1) * 32, wb, tid);
            g2s_h128(Bh, Kq, n0, (i + 1) * 32, wb + TILE_HALVES, tid);
            g2s_h128(Al, Kq, m0, (i + 1) * 32, wb + 2 * TILE_HALVES, tid);
            g2s_h128(Bl, Kq, n0, (i + 1) * 32, wb + 3 * TILE_HALVES, tid);
        }
        CP_COMMIT();
        const uint32_t sA  = smb + (i & 1) * 4 * TILE_HALVES * 2;
        const uint32_t sB  = sA + TILE_HALVES * 2;
        const uint32_t sAl = sA + 2 * TILE_HALVES * 2;
        const uint32_t sBl = sA + 3 * TILE_HALVES * 2;
#pragma unroll
        for (int ks = 0; ks < 2; ks++) {
            const uint32_t ko = ks * 32;
            uint32_t a[4][4], al[4][4];
#pragma unroll
            for (int mi = 0; mi < 4; mi++) {
                ldm4(a[mi],  sA  + aoff + mi * 16 * 80 + ko);
                ldm4(al[mi], sAl + aoff + mi * 16 * 80 + ko);
            }
#pragma unroll
            for (int p = 0; p < 4; p++) {
                uint32_t bh4[4], bl4[4];
                ldm4(bh4, sB  + boff + p * 16 * 80 + ko);
                ldm4(bl4, sBl + boff + p * 16 * 80 + ko);
#pragma unroll
                for (int mi = 0; mi < 4; mi++) {
                    mma16(acc[mi][2 * p],     a[mi],  bh4[0], bh4[1]);
                    mma16(acc[mi][2 * p],     a[mi],  bl4[0], bl4[1]);
                    mma16(acc[mi][2 * p],     al[mi], bh4[0], bh4[1]);
                    mma16(acc[mi][2 * p + 1], a[mi],  bh4[2], bh4[3]);
                    mma16(acc[mi][2 * p + 1], a[mi],  bl4[2], bl4[3]);
                    mma16(acc[mi][2 * p + 1], al[mi], bh4[2], bh4[3]);
                }
            }
        }
    }

#pragma unroll
    for (int mi = 0; mi < 4; mi++) {
#pragma unroll
        for (int ni = 0; ni < 8; ni++) {
            const int row = m0 + wm + mi * 16 + gq;
            const int col = n0 + wn + ni * 8 + 2 * cq;
            *reinterpret_cast<__half2*>(Ch + (size_t)row * Nq + col) =
                __floats2half2_rn(acc[mi][ni][0], acc[mi][ni][1]);
            *reinterpret_cast<__half2*>(Ch + (size_t)(row + 8) * Nq + col) =
                __floats2half2_rn(acc[mi][ni][2], acc[mi][ni][3]);
        }
    }
}

__global__ __launch_bounds__(128, 2) void hgemm_weights(const float* __restrict__ bq) {
    extern __shared__ __half sm[];
    const int bx = blockIdx.x;
    if (bx < 256) {          // W2 = mem @ Wq
        hgemm_core_split(sm, g_mhi, g_mlo, g_wqThi, g_wqTlo, g_w2,
                         (bx >> 3) * 128, (bx & 7) * 128, HD, HD);
    } else if (bx < 512) {   // W3T = Wo @ mem^T
        const int b = bx - 256;
        hgemm_core_split(sm, g_wohi, g_wolo, g_mhi, g_mlo, g_w3T,
                         (b >> 5) * 128, (b & 31) * 128, MMR, HD);
    } else {                 // cvec: c[m] = bq . mem[m]  (128 thr x 8 elems)
        float* sh = reinterpret_cast<float*>(sm);
        const int m = bx - 512, t = threadIdx.x;
        float s = 0.f;
#pragma unroll
        for (int i = 0; i < 8; i++) {
            const int o = t + i * 128;
            s += bq[o] * (__half2float(g_mhi[(size_t)m * HD + o]) +
                          __half2float(g_mlo[(size_t)m * HD + o]));
        }
        sh[t] = s; __syncthreads();
        for (int o = 64; o > 0; o >>= 1) { if (t < o) sh[t] += sh[t + o]; __syncthreads(); }
        if (t == 0) g_cvec[m] = sh[0];
    }
}

// ========== non-split GEMM (KC=64, 3-stage, 128 thr, 64x64 warp tiles) ================
#define RS64 72
#define T64_HALVES (128 * RS64)
#define STG64_HALVES (2 * T64_HALVES)
#define SMEM64 (3 * STG64_HALVES * 2)    // 110592 B, 3 stages

__device__ __forceinline__ void g2s64(const __half* __restrict__ g, int ldh,
                                      int row0, int k0, __half* __restrict__ s, int tid) {
#pragma unroll
    for (int j = 0; j < 8; j++) {
        const int idx = j * 128 + tid;
        const int r = idx >> 3, c = idx & 7;
        cp16(smem_u32(s + r * RS64 + c * 8), g + (size_t)(row0 + r) * ldh + k0 + c * 8);
    }
}

template <bool BIAS, bool RES>
__global__ __launch_bounds__(128, 2) void hgemm64(
    const __half* __restrict__ Ah, const __half* __restrict__ Bh,
    float* __restrict__ Cf, const float* __restrict__ bias,
    const float* __restrict__ res, int Nq, int Kq) {
    extern __shared__ __half sm[];
    const int tid = threadIdx.x;
    const int lane = tid & 31, warp = tid >> 5;
    const int gq = lane >> 2, cq = lane & 3;
    const int wm = (warp >> 1) * 64, wn = (warp & 1) * 64;
    const int m0 = blockIdx.y * 128, n0 = blockIdx.x * 128;
    const int nc = Kq >> 6;

    float acc[4][8][4];
#pragma unroll
    for (int mi = 0; mi < 4; mi++)
#pragma unroll
        for (int ni = 0; ni < 8; ni++)
#pragma unroll
            for (int r = 0; r < 4; r++) acc[mi][ni][r] = 0.f;

#pragma unroll
    for (int p = 0; p < 2; p++) {
        __half* base = sm + p * STG64_HALVES;
        g2s64(Ah, Kq, m0, p * 64, base, tid);
        g2s64(Bh, Kq, n0, p * 64, base + T64_HALVES, tid);
        CP_COMMIT();
    }

    const uint32_t smb = smem_u32(sm);
    const uint32_t aoff = ((lane & 15) * RS64 + (lane >> 4) * 8) * 2 + wm * 144;
    const uint32_t boff = ((((lane >> 4) << 3) + (lane & 7)) * RS64 +
                           ((lane >> 3) & 1) * 8) * 2 + wn * 144;

    for (int i = 0; i < nc; i++) {
        asm volatile("cp.async.wait_group 1;" ::: "memory");
        __syncthreads();
        {
            const int ld = i + 2;
            if (ld < nc) {
                __half* wb = sm + (ld % 3) * STG64_HALVES;
                g2s64(Ah, Kq, m0, ld * 64, wb, tid);
                g2s64(Bh, Kq, n0, ld * 64, wb + T64_HALVES, tid);
            }
            CP_COMMIT();
        }
        const uint32_t sA = smb + (i % 3) * STG64_HALVES * 2;
        const uint32_t sB = sA + T64_HALVES * 2;
#pragma unroll
        for (int ks = 0; ks < 4; ks++) {
            const uint32_t ko = ks * 32;
            uint32_t a[4][4];
#pragma unroll
            for (int mi = 0; mi < 4; mi++)
                ldm4(a[mi], sA + aoff + mi * 16 * 144 + ko);
            uint32_t bf[4][4];
#pragma unroll
            for (int p = 0; p < 4; p++)
                ldm4(bf[p], sB + boff + p * 16 * 144 + ko);
#pragma unroll
            for (int p = 0; p < 4; p++)
#pragma unroll
                for (int mi = 0; mi < 4; mi++) {
                    mma16(acc[mi][2 * p],     a[mi], bf[p][0], bf[p][1]);
                    mma16(acc[mi][2 * p + 1], a[mi], bf[p][2], bf[p][3]);
                }
        }
    }

#pragma unroll
    for (int mi = 0; mi < 4; mi++) {
#pragma unroll
        for (int ni = 0; ni < 8; ni++) {
            const int row = m0 + wm + mi * 16 + gq;
            const int col = n0 + wn + ni * 8 + 2 * cq;
            float2 v0 = make_float2(acc[mi][ni][0], acc[mi][ni][1]);
            float2 v1 = make_float2(acc[mi][ni][2], acc[mi][ni][3]);
            if (BIAS) {
                const float2 bb = *reinterpret_cast<const float2*>(bias + col);
                v0.x += bb.x; v0.y += bb.y; v1.x += bb.x; v1.y += bb.y;
            }
            if (RES) {
                const float2 r0 = *reinterpret_cast<const float2*>(res + (size_t)row * Nq + col);
                const float2 r1 = *reinterpret_cast<const float2*>(res + (size_t)(row + 8) * Nq + col);
                v0.x += r0.x; v0.y += r0.y; v1.x += r1.x; v1.y += r1.y;
            }
            *reinterpret_cast<float2*>(Cf + (size_t)row * Nq + col) = v0;
            *reinterpret_cast<float2*>(Cf + (size_t)(row + 8) * Nq + col) = v1;
        }
    }
}

// ---------------- launch -----------------------------------------------------------------
#define SMEM_WTS (2 * 4 * TILE_HALVES * 2)   // 81920

extern "C" void kernel_launch(void* const* d_in, const int* in_sizes, int n_in,
                              void* d_out, int out_size) {
    const float* hidden = (const float*)d_in[0];
    const float* gam    = (const float*)d_in[1];
    const float* bet    = (const float*)d_in[2];
    const float* Wq     = (const float*)d_in[3];
    const float* bq     = (const float*)d_in[4];
    const float* Wo     = (const float*)d_in[5];
    const float* bo     = (const float*)d_in[6];
    const float* memin  = (const float*)d_in[7];
    const float* imp    = (const float*)d_in[8];
    float* out = (float*)d_out;

    __half *p_nhi, *p_w2, *p_w3T, *p_attn;
    float *p_sim, *p_cvec;
    cudaGetSymbolAddress((void**)&p_nhi, g_nhi);
    cudaGetSymbolAddress((void**)&p_w2, g_w2);
    cudaGetSymbolAddress((void**)&p_w3T, g_w3T);
    cudaGetSymbolAddress((void**)&p_attn, g_attn);
    cudaGetSymbolAddress((void**)&p_sim, g_sim);
    cudaGetSymbolAddress((void**)&p_cvec, g_cvec);

    cudaFuncSetAttribute((const void*)hgemm_weights,
                         cudaFuncAttributeMaxDynamicSharedMemorySize, SMEM_WTS);
    cudaFuncSetAttribute((const void*)hgemm64<true, false>,
                         cudaFuncAttributeMaxDynamicSharedMemorySize, SMEM64);
    cudaFuncSetAttribute((const void*)hgemm64<true, true>,
                         cudaFuncAttributeMaxDynamicSharedMemorySize, SMEM64);

    // 1) prep (mem/Wq/Wo splits) + LayerNorm, fused
    prepln_kernel<<<6144 + NR, 256>>>(memin, Wq, Wo, hidden, gam, bet);
    // 2) both top-K selections concurrently (half-blocks) + scatter
    topk_scatter_kernel<<<1, 1024>>>(imp);
    // 3) weights GEMMs (W2, W3T) + cvec, merged (64x64 warp-tile split core)
    hgemm_weights<<<512 + MMR, 128, SMEM_WTS>>>(bq);
    // 4) sim = norm_hi @ W2^T + c                       <- profiled slot
    {
        dim3 g(MMR / 128, NR / 128);
        hgemm64<true, false><<<g, 128, SMEM64>>>(p_nhi, p_w2, p_sim, p_cvec, nullptr, MMR, HD);
    }
    // 5) softmax -> fp16 attn (block-per-row, 2 barriers)
    softmax_kernel<<<NR, 256>>>();
    // 6) out = attn @ W3T^T + bo + hidden
    {
        dim3 g(HD / 128, NR / 128);
        hgemm64<true, true><<<g, 128, SMEM64>>>(p_attn, p_w3T, out, bo, hidden, HD, MMR);
    }
}